// round 5
// baseline (speedup 1.0000x reference)
#include <cuda_runtime.h>
#include <cuda_bf16.h>
#include <cstdint>

// ============================================================================
// KoopmanOperator: z_{t+1} = z + DT*(z@A^T + sum_l a_l * U_l (V_l^T z))
// N=262144 rows, m=256, da=6, r=16, steps=8.
//
// Plain-target (compute_103) implementation: warp-level mma.sync bf16 HMMA.
// z is the fp32 accumulator in registers for all steps (identity exact).
// Weights are precomputed into fragment-ordered SMEM images.
// ============================================================================

#define DT_C    0.1f
#define BMAX_C  0.3f

static constexpr int M_DIM  = 256;
static constexpr int TILE_M = 128;   // rows per CTA (8 warps x 16)

// Fragment-ordered weight images. Each "frag pair" = [lane 32][4 x u32] = 512B,
// holding B-fragments for two adjacent k-chunks (kc=2*kc2, 2*kc2+1).
//   BA: DT*A      kc2 in [0,8), nc in [0,32)   -> 8*32*512 = 131072 B
//   BV: tanh(V)*B kc2 in [0,8), nc in [0,12)   -> 8*12*512 =  49152 B
//   BU: DT*tanh(U)*B kc2 in [0,3), nc in [0,32)-> 3*32*512 =  49152 B
static constexpr int BA_BYTES = 8 * 32 * 512;
static constexpr int BV_BYTES = 8 * 12 * 512;
static constexpr int BU_BYTES = 3 * 32 * 512;
static constexpr int W_TOTAL  = BA_BYTES + BV_BYTES + BU_BYTES;  // 229376

__device__ __align__(16) unsigned char g_wfrag[W_TOTAL];

// ============================================================================
// helpers
// ============================================================================
__device__ __forceinline__ uint32_t smem_u32(const void* p) {
    uint32_t a;
    asm("{ .reg .u64 t; cvta.to.shared.u64 t, %1; cvt.u32.u64 %0, t; }"
        : "=r"(a) : "l"(p));
    return a;
}

// pack(lo, hi): lo -> low 16 bits. PTX cvt.bf16x2: first src -> HIGH half.
__device__ __forceinline__ uint32_t packbf(float lo, float hi) {
    uint32_t r;
    asm("cvt.rn.satfinite.bf16x2.f32 %0, %1, %2;" : "=r"(r) : "f"(hi), "f"(lo));
    return r;
}

__device__ __forceinline__ void lds128(uint32_t& x, uint32_t& y,
                                       uint32_t& z, uint32_t& w, uint32_t addr) {
    asm volatile("ld.shared.v4.b32 {%0,%1,%2,%3}, [%4];"
                 : "=r"(x), "=r"(y), "=r"(z), "=r"(w) : "r"(addr));
}

__device__ __forceinline__ void mma_bf16(float& d0, float& d1, float& d2, float& d3,
                                         uint32_t a0, uint32_t a1, uint32_t a2,
                                         uint32_t a3, uint32_t b0, uint32_t b1) {
    asm volatile(
        "mma.sync.aligned.m16n8k16.row.col.f32.bf16.bf16.f32 "
        "{%0,%1,%2,%3}, {%4,%5,%6,%7}, {%8,%9}, {%0,%1,%2,%3};"
        : "+f"(d0), "+f"(d1), "+f"(d2), "+f"(d3)
        : "r"(a0), "r"(a1), "r"(a2), "r"(a3), "r"(b0), "r"(b1));
}

// ============================================================================
// Precompute: build fragment-ordered bf16 weight images in g_wfrag.
// B-fragment (m16n8k16, row.col): lane l, reg b0 = {B[k0][n], B[k0+1][n]},
// b1 = {B[k0+8][n], B[k0+9][n]}, with n = 8*nc + (l>>2), k0 = 16*kc + (l&3)*2.
// u32 id nesting (innermost first): r(4) -> lane(32) -> nc -> kc2.
//   r = {kc even: b0, b1, kc odd: b0, b1}  i.e. kc = 2*kc2 + (r>>1), breg = r&1.
// ============================================================================
__global__ void koop_pre(const float* __restrict__ A,
                         const float* __restrict__ BU,
                         const float* __restrict__ BV) {
    int id = blockIdx.x * blockDim.x + threadIdx.x;
    if (id >= W_TOTAL / 4) return;

    int r    = id & 3;
    int lane = (id >> 2) & 31;
    int rest = id >> 7;
    int tig = lane & 3, lg = lane >> 2;
    int kodd = r >> 1, breg = r & 1;

    float lo, hi;
    if (id < BA_BYTES / 4) {
        int nc = rest & 31, kc2 = rest >> 5;
        int n  = 8 * nc + lg;
        int k0 = 16 * (2 * kc2 + kodd) + tig * 2 + breg * 8;
        lo = DT_C * A[n * 256 + k0];
        hi = DT_C * A[n * 256 + k0 + 1];
    } else if (id < (BA_BYTES + BV_BYTES) / 4) {
        int rest2 = rest - (BA_BYTES / 512);      // BA has 8*32=256 frag-pairs
        int nc = rest2 % 12, kc2 = rest2 / 12;
        int n  = 8 * nc + lg;                     // n = l_idx*16 + r_idx, [0,96)
        int k0 = 16 * (2 * kc2 + kodd) + tig * 2 + breg * 8;
        int l_idx = n >> 4, r_idx = n & 15;
        lo = tanhf(BV[(l_idx * 256 + k0)     * 16 + r_idx]) * BMAX_C;
        hi = tanhf(BV[(l_idx * 256 + k0 + 1) * 16 + r_idx]) * BMAX_C;
    } else {
        int rest3 = rest - ((BA_BYTES + BV_BYTES) / 512);
        int nc = rest3 & 31, kc2 = rest3 >> 5;    // kc2 in [0,3)
        int n  = 8 * nc + lg;                     // output col [0,256)
        int k0 = 16 * (2 * kc2 + kodd) + tig * 2 + breg * 8;   // [0,96)
        int l0 = k0 >> 4,       r0i = k0 & 15;
        int l1 = (k0 + 1) >> 4, r1i = (k0 + 1) & 15;
        lo = DT_C * tanhf(BU[(l0 * 256 + n) * 16 + r0i]) * BMAX_C;
        hi = DT_C * tanhf(BU[(l1 * 256 + n) * 16 + r1i]) * BMAX_C;
    }
    reinterpret_cast<uint32_t*>(g_wfrag)[id] = packbf(lo, hi);
}

// ============================================================================
// Main persistent kernel: 256 threads (8 warps), each warp owns 16 rows.
// No CTA-wide sync in the hot loop — everything is warp-local.
// ============================================================================
__global__ void __launch_bounds__(256, 1)
koop_main(const float* __restrict__ z_in, const float* __restrict__ a_in,
          const int* __restrict__ steps_p, float* __restrict__ out, int n_tiles) {
    extern __shared__ unsigned char smem[];
    int tid = threadIdx.x, wid = tid >> 5, lane = tid & 31;
    int tig = lane & 3, lg = lane >> 2;

    // Load weight images into SMEM once (uint4 vectorized).
    {
        const uint4* src = reinterpret_cast<const uint4*>(g_wfrag);
        uint4* dst = reinterpret_cast<uint4*>(smem);
        for (int i = tid; i < W_TOTAL / 16; i += 256) dst[i] = src[i];
    }
    __syncthreads();

    const uint32_t sb  = smem_u32(smem);
    const uint32_t sbV = sb + BA_BYTES;
    const uint32_t sbU = sb + BA_BYTES + BV_BYTES;
    const uint32_t lane16 = (uint32_t)lane * 16;
    const int steps = steps_p ? *steps_p : 8;

    for (int tile = blockIdx.x; tile < n_tiles; tile += gridDim.x) {
        int r0 = tile * TILE_M + wid * 16 + lg;   // this thread's row (c0/c1)
        const float2* zr0 = reinterpret_cast<const float2*>(z_in + (size_t)r0 * M_DIM);
        const float2* zr1 = reinterpret_cast<const float2*>(z_in + (size_t)(r0 + 8) * M_DIM);

        // acc = z in D-fragment layout: acc[nc] covers cols [8nc, 8nc+8);
        // c0,c1 = row r0 cols 8nc+2*tig,+1 ; c2,c3 = row r0+8.
        float acc[32][4];
#pragma unroll
        for (int nc = 0; nc < 32; nc++) {
            float2 v0 = zr0[4 * nc + tig];
            float2 v1 = zr1[4 * nc + tig];
            acc[nc][0] = v0.x; acc[nc][1] = v0.y;
            acc[nc][2] = v1.x; acc[nc][3] = v1.y;
        }
        float av0[6], av1[6];
#pragma unroll
        for (int l = 0; l < 6; l++) {
            av0[l] = a_in[(size_t)r0 * 6 + l];
            av1[l] = a_in[(size_t)(r0 + 8) * 6 + l];
        }

#pragma unroll 1
        for (int s = 0; s < steps; s++) {
            // ---- bf16 A-fragments of current z, straight from acc ----
            uint32_t af[16][4];
#pragma unroll
            for (int kc = 0; kc < 16; kc++) {
                af[kc][0] = packbf(acc[2 * kc][0],     acc[2 * kc][1]);
                af[kc][1] = packbf(acc[2 * kc][2],     acc[2 * kc][3]);
                af[kc][2] = packbf(acc[2 * kc + 1][0], acc[2 * kc + 1][1]);
                af[kc][3] = packbf(acc[2 * kc + 1][2], acc[2 * kc + 1][3]);
            }

            // ---- proj = z @ Vc  (N=96), scale by a_l, pack into pa A-frags ----
            uint32_t paf[6][4];
#pragma unroll
            for (int nc = 0; nc < 12; nc++) {
                float p0 = 0.f, p1 = 0.f, p2 = 0.f, p3 = 0.f;
#pragma unroll
                for (int kc2 = 0; kc2 < 8; kc2++) {
                    uint32_t b0, b1, b2, b3;
                    lds128(b0, b1, b2, b3,
                           sbV + (uint32_t)(kc2 * 12 + nc) * 512 + lane16);
                    mma_bf16(p0, p1, p2, p3,
                             af[2 * kc2][0], af[2 * kc2][1],
                             af[2 * kc2][2], af[2 * kc2][3], b0, b1);
                    mma_bf16(p0, p1, p2, p3,
                             af[2 * kc2 + 1][0], af[2 * kc2 + 1][1],
                             af[2 * kc2 + 1][2], af[2 * kc2 + 1][3], b2, b3);
                }
                int g = nc >> 1;                 // a-index: proj col / 16
                uint32_t u0 = packbf(p0 * av0[g], p1 * av0[g]);
                uint32_t u1 = packbf(p2 * av1[g], p3 * av1[g]);
                if (nc & 1) { paf[nc >> 1][2] = u0; paf[nc >> 1][3] = u1; }
                else        { paf[nc >> 1][0] = u0; paf[nc >> 1][1] = u1; }
            }

            // ---- acc += z @ (DT*A)^T  (N=256, K=256) ----
#pragma unroll
            for (int kc2 = 0; kc2 < 8; kc2++) {
#pragma unroll
                for (int nc = 0; nc < 32; nc++) {
                    uint32_t b0, b1, b2, b3;
                    lds128(b0, b1, b2, b3,
                           sb + (uint32_t)(kc2 * 32 + nc) * 512 + lane16);
                    mma_bf16(acc[nc][0], acc[nc][1], acc[nc][2], acc[nc][3],
                             af[2 * kc2][0], af[2 * kc2][1],
                             af[2 * kc2][2], af[2 * kc2][3], b0, b1);
                    mma_bf16(acc[nc][0], acc[nc][1], acc[nc][2], acc[nc][3],
                             af[2 * kc2 + 1][0], af[2 * kc2 + 1][1],
                             af[2 * kc2 + 1][2], af[2 * kc2 + 1][3], b2, b3);
                }
            }

            // ---- acc += pa @ (DT*Uc)^T  (N=256, K=96) ----
#pragma unroll
            for (int kc2 = 0; kc2 < 3; kc2++) {
#pragma unroll
                for (int nc = 0; nc < 32; nc++) {
                    uint32_t b0, b1, b2, b3;
                    lds128(b0, b1, b2, b3,
                           sbU + (uint32_t)(kc2 * 32 + nc) * 512 + lane16);
                    mma_bf16(acc[nc][0], acc[nc][1], acc[nc][2], acc[nc][3],
                             paf[2 * kc2][0], paf[2 * kc2][1],
                             paf[2 * kc2][2], paf[2 * kc2][3], b0, b1);
                    mma_bf16(acc[nc][0], acc[nc][1], acc[nc][2], acc[nc][3],
                             paf[2 * kc2 + 1][0], paf[2 * kc2 + 1][1],
                             paf[2 * kc2 + 1][2], paf[2 * kc2 + 1][3], b2, b3);
                }
            }
        }

        // ---- store result ----
        float2* o0 = reinterpret_cast<float2*>(out + (size_t)r0 * M_DIM);
        float2* o1 = reinterpret_cast<float2*>(out + (size_t)(r0 + 8) * M_DIM);
#pragma unroll
        for (int nc = 0; nc < 32; nc++) {
            o0[4 * nc + tig] = make_float2(acc[nc][0], acc[nc][1]);
            o1[4 * nc + tig] = make_float2(acc[nc][2], acc[nc][3]);
        }
    }
}

// ============================================================================
// kernel_launch — graph-capturable: two kernel launches, no sync, no alloc.
// ============================================================================
extern "C" void kernel_launch(void* const* d_in, const int* in_sizes, int n_in,
                              void* d_out, int out_size) {
    const float* z  = (const float*)d_in[0];
    const float* a  = (const float*)d_in[1];
    const float* A  = (const float*)d_in[2];
    const float* BU = (const float*)d_in[3];
    const float* BV = (const float*)d_in[4];
    const int* steps = (n_in > 5) ? (const int*)d_in[5] : nullptr;

    int n_rows  = in_sizes[0] / M_DIM;
    int n_tiles = n_rows / TILE_M;

    cudaFuncSetAttribute(koop_main, cudaFuncAttributeMaxDynamicSharedMemorySize,
                         W_TOTAL);

    int pre_threads = W_TOTAL / 4;
    koop_pre<<<(pre_threads + 255) / 256, 256>>>(A, BU, BV);

    int dev = 0, sm_count = 0;
    cudaGetDevice(&dev);
    cudaDeviceGetAttribute(&sm_count, cudaDevAttrMultiProcessorCount, dev);
    if (sm_count <= 0) sm_count = 148;
    int grid = n_tiles < sm_count ? n_tiles : sm_count;

    koop_main<<<grid, 256, W_TOTAL>>>(z, a, steps, (float*)d_out, n_tiles);
}

// round 6
// speedup vs baseline: 1.0043x; 1.0043x over previous
#include <cuda_runtime.h>
#include <cuda_bf16.h>
#include <cstdint>

// ============================================================================
// KoopmanOperator: z_{t+1} = z + DT*(z@A^T + sum_l a_l * U_l (V_l^T z))
// N=262144 rows, m=256, da=6, r=16, steps=8.
//
// mma.sync bf16 HMMA; z is the fp32 D-fragment accumulator across all steps
// (identity term exact). Weights precomputed into fragment-ordered SMEM
// images. R6: loop reorder (A before V), nc-pair V-proj (small p live range),
// depth-2 software prefetch in the A-GEMM loop.
// ============================================================================

#define DT_C    0.1f
#define BMAX_C  0.3f

static constexpr int M_DIM  = 256;
static constexpr int TILE_M = 128;   // rows per CTA (8 warps x 16)

// Fragment-ordered weight images. Each "frag pair" = [lane 32][4 x u32] = 512B,
// holding B-fragments for two adjacent k-chunks (kc=2*kc2, 2*kc2+1).
//   BA: DT*A      kc2 in [0,8), nc in [0,32)   -> 8*32*512 = 131072 B
//   BV: tanh(V)*B kc2 in [0,8), nc in [0,12)   -> 8*12*512 =  49152 B
//   BU: DT*tanh(U)*B kc2 in [0,3), nc in [0,32)-> 3*32*512 =  49152 B
static constexpr int BA_BYTES = 8 * 32 * 512;
static constexpr int BV_BYTES = 8 * 12 * 512;
static constexpr int BU_BYTES = 3 * 32 * 512;
static constexpr int W_TOTAL  = BA_BYTES + BV_BYTES + BU_BYTES;  // 229376

__device__ __align__(16) unsigned char g_wfrag[W_TOTAL];

// ============================================================================
// helpers
// ============================================================================
__device__ __forceinline__ uint32_t smem_u32(const void* p) {
    uint32_t a;
    asm("{ .reg .u64 t; cvta.to.shared.u64 t, %1; cvt.u32.u64 %0, t; }"
        : "=r"(a) : "l"(p));
    return a;
}

// pack(lo, hi): lo -> low 16 bits. PTX cvt.bf16x2: first src -> HIGH half.
__device__ __forceinline__ uint32_t packbf(float lo, float hi) {
    uint32_t r;
    asm("cvt.rn.satfinite.bf16x2.f32 %0, %1, %2;" : "=r"(r) : "f"(hi), "f"(lo));
    return r;
}

__device__ __forceinline__ void lds128(uint32_t& x, uint32_t& y,
                                       uint32_t& z, uint32_t& w, uint32_t addr) {
    asm volatile("ld.shared.v4.b32 {%0,%1,%2,%3}, [%4];"
                 : "=r"(x), "=r"(y), "=r"(z), "=r"(w) : "r"(addr));
}

__device__ __forceinline__ void mma_bf16(float& d0, float& d1, float& d2, float& d3,
                                         uint32_t a0, uint32_t a1, uint32_t a2,
                                         uint32_t a3, uint32_t b0, uint32_t b1) {
    asm volatile(
        "mma.sync.aligned.m16n8k16.row.col.f32.bf16.bf16.f32 "
        "{%0,%1,%2,%3}, {%4,%5,%6,%7}, {%8,%9}, {%0,%1,%2,%3};"
        : "+f"(d0), "+f"(d1), "+f"(d2), "+f"(d3)
        : "r"(a0), "r"(a1), "r"(a2), "r"(a3), "r"(b0), "r"(b1));
}

// ============================================================================
// Precompute: build fragment-ordered bf16 weight images in g_wfrag.
// B-fragment (m16n8k16, row.col): lane l, reg b0 = {B[k0][n], B[k0+1][n]},
// b1 = {B[k0+8][n], B[k0+9][n]}, with n = 8*nc + (l>>2), k0 = 16*kc + (l&3)*2.
// u32 id nesting (innermost first): r(4) -> lane(32) -> nc -> kc2.
//   kc = 2*kc2 + (r>>1), breg = r&1.
// ============================================================================
__global__ void koop_pre(const float* __restrict__ A,
                         const float* __restrict__ BU,
                         const float* __restrict__ BV) {
    int id = blockIdx.x * blockDim.x + threadIdx.x;
    if (id >= W_TOTAL / 4) return;

    int r    = id & 3;
    int lane = (id >> 2) & 31;
    int rest = id >> 7;
    int tig = lane & 3, lg = lane >> 2;
    int kodd = r >> 1, breg = r & 1;

    float lo, hi;
    if (id < BA_BYTES / 4) {
        int nc = rest & 31, kc2 = rest >> 5;
        int n  = 8 * nc + lg;
        int k0 = 16 * (2 * kc2 + kodd) + tig * 2 + breg * 8;
        lo = DT_C * A[n * 256 + k0];
        hi = DT_C * A[n * 256 + k0 + 1];
    } else if (id < (BA_BYTES + BV_BYTES) / 4) {
        int rest2 = rest - (BA_BYTES / 512);
        int nc = rest2 % 12, kc2 = rest2 / 12;
        int n  = 8 * nc + lg;                     // n = l_idx*16 + r_idx, [0,96)
        int k0 = 16 * (2 * kc2 + kodd) + tig * 2 + breg * 8;
        int l_idx = n >> 4, r_idx = n & 15;
        lo = tanhf(BV[(l_idx * 256 + k0)     * 16 + r_idx]) * BMAX_C;
        hi = tanhf(BV[(l_idx * 256 + k0 + 1) * 16 + r_idx]) * BMAX_C;
    } else {
        int rest3 = rest - ((BA_BYTES + BV_BYTES) / 512);
        int nc = rest3 & 31, kc2 = rest3 >> 5;    // kc2 in [0,3)
        int n  = 8 * nc + lg;                     // output col [0,256)
        int k0 = 16 * (2 * kc2 + kodd) + tig * 2 + breg * 8;   // [0,96)
        int l0 = k0 >> 4,       r0i = k0 & 15;
        int l1 = (k0 + 1) >> 4, r1i = (k0 + 1) & 15;
        lo = DT_C * tanhf(BU[(l0 * 256 + n) * 16 + r0i]) * BMAX_C;
        hi = DT_C * tanhf(BU[(l1 * 256 + n) * 16 + r1i]) * BMAX_C;
    }
    reinterpret_cast<uint32_t*>(g_wfrag)[id] = packbf(lo, hi);
}

// ============================================================================
// Main persistent kernel: 256 threads (8 warps), each warp owns 16 rows.
// No CTA-wide sync in the hot loop — everything is warp-local.
// ============================================================================
__global__ void __launch_bounds__(256, 1)
koop_main(const float* __restrict__ z_in, const float* __restrict__ a_in,
          const int* __restrict__ steps_p, float* __restrict__ out, int n_tiles) {
    extern __shared__ unsigned char smem[];
    int tid = threadIdx.x, wid = tid >> 5, lane = tid & 31;
    int tig = lane & 3, lg = lane >> 2;

    // Load weight images into SMEM once (uint4 vectorized).
    {
        const uint4* src = reinterpret_cast<const uint4*>(g_wfrag);
        uint4* dst = reinterpret_cast<uint4*>(smem);
        for (int i = tid; i < W_TOTAL / 16; i += 256) dst[i] = src[i];
    }
    __syncthreads();

    const uint32_t sbA = smem_u32(smem) + (uint32_t)lane * 16;
    const uint32_t sbV = sbA + BA_BYTES;
    const uint32_t sbU = sbA + BA_BYTES + BV_BYTES;
    const int steps = steps_p ? *steps_p : 8;

    for (int tile = blockIdx.x; tile < n_tiles; tile += gridDim.x) {
        int r0 = tile * TILE_M + wid * 16 + lg;
        const float2* zr0 = reinterpret_cast<const float2*>(z_in + (size_t)r0 * M_DIM);
        const float2* zr1 = reinterpret_cast<const float2*>(z_in + (size_t)(r0 + 8) * M_DIM);

        // acc = z in D-fragment layout: acc[nc] covers cols [8nc, 8nc+8);
        // [0],[1] = row r0 cols 8nc+2tig,+1 ; [2],[3] = row r0+8.
        float acc[32][4];
#pragma unroll
        for (int nc = 0; nc < 32; nc++) {
            float2 v0 = zr0[4 * nc + tig];
            float2 v1 = zr1[4 * nc + tig];
            acc[nc][0] = v0.x; acc[nc][1] = v0.y;
            acc[nc][2] = v1.x; acc[nc][3] = v1.y;
        }
        float av0[6], av1[6];
#pragma unroll
        for (int l = 0; l < 6; l++) {
            av0[l] = a_in[(size_t)r0 * 6 + l];
            av1[l] = a_in[(size_t)(r0 + 8) * 6 + l];
        }

#pragma unroll 1
        for (int s = 0; s < steps; s++) {
            // ---- snapshot old z as bf16 A-fragments (af = 64 u32) ----
            uint32_t af[16][4];
#pragma unroll
            for (int kc = 0; kc < 16; kc++) {
                af[kc][0] = packbf(acc[2 * kc][0],     acc[2 * kc][1]);
                af[kc][1] = packbf(acc[2 * kc][2],     acc[2 * kc][3]);
                af[kc][2] = packbf(acc[2 * kc + 1][0], acc[2 * kc + 1][1]);
                af[kc][3] = packbf(acc[2 * kc + 1][2], acc[2 * kc + 1][3]);
            }

            // ---- A-GEMM: acc += z @ (DT*A)^T  (N=256, K=256) ----
            // Flattened 256-iter loop with depth-2 B prefetch: i = kc2*32+nc.
            {
                uint32_t b0[4], b1[4], b2[4];
                lds128(b0[0], b0[1], b0[2], b0[3], sbA);
                lds128(b1[0], b1[1], b1[2], b1[3], sbA + 512);
#pragma unroll
                for (int i = 0; i < 256; i++) {
                    if (i + 2 < 256)
                        lds128(b2[0], b2[1], b2[2], b2[3],
                               sbA + (uint32_t)(i + 2) * 512);
                    int kc2 = i >> 5, nc = i & 31;
                    mma_bf16(acc[nc][0], acc[nc][1], acc[nc][2], acc[nc][3],
                             af[2 * kc2][0], af[2 * kc2][1],
                             af[2 * kc2][2], af[2 * kc2][3], b0[0], b0[1]);
                    mma_bf16(acc[nc][0], acc[nc][1], acc[nc][2], acc[nc][3],
                             af[2 * kc2 + 1][0], af[2 * kc2 + 1][1],
                             af[2 * kc2 + 1][2], af[2 * kc2 + 1][3], b0[2], b0[3]);
#pragma unroll
                    for (int q = 0; q < 4; q++) { b0[q] = b1[q]; b1[q] = b2[q]; }
                }
            }

            // ---- V-proj: proj = z @ Vc^T (N=96), scale by a_l, pack paf ----
            // nc-pair outer: only 8 fp32 proj accumulators live at a time.
            uint32_t paf[6][4];
#pragma unroll
            for (int ncp = 0; ncp < 6; ncp++) {
                float p0[4] = {0.f, 0.f, 0.f, 0.f};
                float p1[4] = {0.f, 0.f, 0.f, 0.f};
                uint32_t c0[4], c1[4], n0[4], n1[4];
                lds128(c0[0], c0[1], c0[2], c0[3], sbV + (uint32_t)(2 * ncp) * 512);
                lds128(c1[0], c1[1], c1[2], c1[3], sbV + (uint32_t)(2 * ncp + 1) * 512);
#pragma unroll
                for (int kc2 = 0; kc2 < 8; kc2++) {
                    if (kc2 + 1 < 8) {
                        uint32_t base = sbV + (uint32_t)((kc2 + 1) * 12 + 2 * ncp) * 512;
                        lds128(n0[0], n0[1], n0[2], n0[3], base);
                        lds128(n1[0], n1[1], n1[2], n1[3], base + 512);
                    }
                    mma_bf16(p0[0], p0[1], p0[2], p0[3],
                             af[2 * kc2][0], af[2 * kc2][1],
                             af[2 * kc2][2], af[2 * kc2][3], c0[0], c0[1]);
                    mma_bf16(p0[0], p0[1], p0[2], p0[3],
                             af[2 * kc2 + 1][0], af[2 * kc2 + 1][1],
                             af[2 * kc2 + 1][2], af[2 * kc2 + 1][3], c0[2], c0[3]);
                    mma_bf16(p1[0], p1[1], p1[2], p1[3],
                             af[2 * kc2][0], af[2 * kc2][1],
                             af[2 * kc2][2], af[2 * kc2][3], c1[0], c1[1]);
                    mma_bf16(p1[0], p1[1], p1[2], p1[3],
                             af[2 * kc2 + 1][0], af[2 * kc2 + 1][1],
                             af[2 * kc2 + 1][2], af[2 * kc2 + 1][3], c1[2], c1[3]);
#pragma unroll
                    for (int q = 0; q < 4; q++) { c0[q] = n0[q]; c1[q] = n1[q]; }
                }
                // a-group for proj cols [16ncp,16ncp+16) is ncp for both nc's.
                paf[ncp][0] = packbf(p0[0] * av0[ncp], p0[1] * av0[ncp]);
                paf[ncp][1] = packbf(p0[2] * av1[ncp], p0[3] * av1[ncp]);
                paf[ncp][2] = packbf(p1[0] * av0[ncp], p1[1] * av0[ncp]);
                paf[ncp][3] = packbf(p1[2] * av1[ncp], p1[3] * av1[ncp]);
            }

            // ---- U-GEMM: acc += pa @ (DT*Uc)^T  (N=256, K=96) ----
            {
                uint32_t b0[4], b1[4], b2[4];
                lds128(b0[0], b0[1], b0[2], b0[3], sbU);
                lds128(b1[0], b1[1], b1[2], b1[3], sbU + 512);
#pragma unroll
                for (int i = 0; i < 96; i++) {
                    if (i + 2 < 96)
                        lds128(b2[0], b2[1], b2[2], b2[3],
                               sbU + (uint32_t)(i + 2) * 512);
                    int kc2 = i >> 5, nc = i & 31;
                    mma_bf16(acc[nc][0], acc[nc][1], acc[nc][2], acc[nc][3],
                             paf[2 * kc2][0], paf[2 * kc2][1],
                             paf[2 * kc2][2], paf[2 * kc2][3], b0[0], b0[1]);
                    mma_bf16(acc[nc][0], acc[nc][1], acc[nc][2], acc[nc][3],
                             paf[2 * kc2 + 1][0], paf[2 * kc2 + 1][1],
                             paf[2 * kc2 + 1][2], paf[2 * kc2 + 1][3], b0[2], b0[3]);
#pragma unroll
                    for (int q = 0; q < 4; q++) { b0[q] = b1[q]; b1[q] = b2[q]; }
                }
            }
        }

        // ---- store result ----
        float2* o0 = reinterpret_cast<float2*>(out + (size_t)r0 * M_DIM);
        float2* o1 = reinterpret_cast<float2*>(out + (size_t)(r0 + 8) * M_DIM);
#pragma unroll
        for (int nc = 0; nc < 32; nc++) {
            o0[4 * nc + tig] = make_float2(acc[nc][0], acc[nc][1]);
            o1[4 * nc + tig] = make_float2(acc[nc][2], acc[nc][3]);
        }
    }
}

// ============================================================================
// kernel_launch — graph-capturable: two kernel launches, no sync, no alloc.
// ============================================================================
extern "C" void kernel_launch(void* const* d_in, const int* in_sizes, int n_in,
                              void* d_out, int out_size) {
    const float* z  = (const float*)d_in[0];
    const float* a  = (const float*)d_in[1];
    const float* A  = (const float*)d_in[2];
    const float* BU = (const float*)d_in[3];
    const float* BV = (const float*)d_in[4];
    const int* steps = (n_in > 5) ? (const int*)d_in[5] : nullptr;

    int n_rows  = in_sizes[0] / M_DIM;
    int n_tiles = n_rows / TILE_M;

    cudaFuncSetAttribute(koop_main, cudaFuncAttributeMaxDynamicSharedMemorySize,
                         W_TOTAL);

    int pre_threads = W_TOTAL / 4;
    koop_pre<<<(pre_threads + 255) / 256, 256>>>(A, BU, BV);

    int dev = 0, sm_count = 0;
    cudaGetDevice(&dev);
    cudaDeviceGetAttribute(&sm_count, cudaDevAttrMultiProcessorCount, dev);
    if (sm_count <= 0) sm_count = 148;
    int grid = n_tiles < sm_count ? n_tiles : sm_count;

    koop_main<<<grid, 256, W_TOTAL>>>(z, a, steps, (float*)d_out, n_tiles);
}